// round 1
// baseline (speedup 1.0000x reference)
#include <cuda_runtime.h>
#include <cuda_bf16.h>
#include <math.h>

// ---------------------------------------------------------------------------
// GraphAttentionInfluence: 2-layer GAT (Hh=4/Hd=256 then H=1/Hd=256) +
// mean-pool + 2-layer MLP sigmoid head.
// Pipeline:
//   CSR build (hist/scan/scatter on dst with self loops)
//   SGEMM h1 = x@W1            [N,1024]
//   logits s_src/s_dst (dot with a_src/a_dst)
//   attn (per-dst-node block): segment softmax + aggregation + bias + ELU
//   SGEMM h2 = h1p@W2          [N,256]
//   logits + attn (H=1) -> d_out h region
//   mean pool -> gf
//   SGEMM t = relu(h@Wp1+bp1)  [N,128]
//   infl = sigmoid(t@Wp2+bp2)  [N,1]
// ---------------------------------------------------------------------------

#define N_MAX   20480
#define E_MAX   327680
#define ETOT_MAX (N_MAX + E_MAX)

__device__ float g_h1 [(size_t)N_MAX * 1024];
__device__ float g_h1p[(size_t)N_MAX * 1024];
__device__ float g_h2 [(size_t)N_MAX * 256];
__device__ float g_t  [(size_t)N_MAX * 128];
__device__ float g_alpha[(size_t)ETOT_MAX * 4];
__device__ float g_ss[N_MAX * 4];
__device__ float g_sd[N_MAX * 4];
__device__ int   g_deg[N_MAX];
__device__ int   g_cnt[N_MAX];
__device__ int   g_rowptr[N_MAX + 1];
__device__ int   g_csrc[ETOT_MAX];

// ---- monotonic float<->uint encoding for atomicMax on floats --------------
__device__ __forceinline__ unsigned fenc(float f) {
    unsigned u = __float_as_uint(f);
    return (u >> 31) ? ~u : (u | 0x80000000u);
}
__device__ __forceinline__ float fdec(unsigned u) {
    return (u >> 31) ? __uint_as_float(u & 0x7FFFFFFFu) : __uint_as_float(~u);
}

// ---------------------------------------------------------------------------
// CSR build kernels
// ---------------------------------------------------------------------------
__global__ void zero2_kernel(int* a, int* b, int n) {
    int i = blockIdx.x * 256 + threadIdx.x;
    if (i < n) { a[i] = 0; b[i] = 0; }
}

__global__ void hist_kernel(const int* __restrict__ dst, int E, int N, int* __restrict__ deg) {
    int e = blockIdx.x * 256 + threadIdx.x;
    int Etot = E + N;
    if (e < Etot) {
        int d = (e < E) ? dst[e] : (e - E);
        atomicAdd(&deg[d], 1);
    }
}

__global__ void scan_kernel(const int* __restrict__ deg, int* __restrict__ rowptr, int N, int Etot) {
    __shared__ int part[1024];
    int tid = threadIdx.x;
    int chunk = (N + 1023) >> 10;
    int lo = tid * chunk;
    int hi = min(lo + chunk, N);
    int s = 0;
    for (int i = lo; i < hi; i++) s += deg[i];
    part[tid] = s;
    __syncthreads();
    for (int off = 1; off < 1024; off <<= 1) {
        int v = (tid >= off) ? part[tid - off] : 0;
        __syncthreads();
        part[tid] += v;
        __syncthreads();
    }
    int run = tid ? part[tid - 1] : 0;
    for (int i = lo; i < hi; i++) { rowptr[i] = run; run += deg[i]; }
    if (tid == 0) rowptr[N] = Etot;
}

__global__ void scatter_kernel(const int* __restrict__ src, const int* __restrict__ dst,
                               int E, int N, const int* __restrict__ rowptr,
                               int* __restrict__ cnt, int* __restrict__ csrc) {
    int e = blockIdx.x * 256 + threadIdx.x;
    int Etot = E + N;
    if (e < Etot) {
        int d, s;
        if (e < E) { d = dst[e]; s = src[e]; }
        else       { d = e - E;  s = e - E;  }
        int pos = rowptr[d] + atomicAdd(&cnt[d], 1);
        csrc[pos] = s;
    }
}

// ---------------------------------------------------------------------------
// SGEMM: C[M,N] = A[M,K] @ B[K,N], row-major; optional bias + relu.
// BM=BN=128, BK=16, 256 threads, 8x8 per-thread microtile.
// Requires N % 128 == 0, K % 16 == 0 (true for all calls here).
// ---------------------------------------------------------------------------
__global__ __launch_bounds__(256, 2)
void sgemm_kernel(const float* __restrict__ A, const float* __restrict__ B,
                  float* __restrict__ C, int M, int N, int K,
                  const float* __restrict__ bias, int act) {
    __shared__ float As[16][128];
    __shared__ float Bs[16][128];
    int tid = threadIdx.x;
    int bm = blockIdx.y * 128;
    int bn = blockIdx.x * 128;
    int tr = (tid >> 4) * 8;
    int tc = (tid & 15) * 8;

    float acc[8][8];
#pragma unroll
    for (int i = 0; i < 8; i++)
#pragma unroll
        for (int j = 0; j < 8; j++) acc[i][j] = 0.f;

    int arow = tid >> 2;          // 0..63
    int acol = (tid & 3) * 4;     // 0,4,8,12
    int brow = tid >> 5;          // 0..7
    int bcol = (tid & 31) * 4;    // 0..124

    for (int k0 = 0; k0 < K; k0 += 16) {
#pragma unroll
        for (int i = 0; i < 2; i++) {
            int r = arow + i * 64;
            float4 v = make_float4(0.f, 0.f, 0.f, 0.f);
            if (bm + r < M)
                v = *reinterpret_cast<const float4*>(&A[(size_t)(bm + r) * K + k0 + acol]);
            As[acol + 0][r] = v.x;
            As[acol + 1][r] = v.y;
            As[acol + 2][r] = v.z;
            As[acol + 3][r] = v.w;
        }
#pragma unroll
        for (int i = 0; i < 2; i++) {
            int r = brow + i * 8;
            float4 v = *reinterpret_cast<const float4*>(&B[(size_t)(k0 + r) * N + bn + bcol]);
            *reinterpret_cast<float4*>(&Bs[r][bcol]) = v;
        }
        __syncthreads();
#pragma unroll
        for (int k = 0; k < 16; k++) {
            float ra[8], rb[8];
#pragma unroll
            for (int i = 0; i < 8; i++) ra[i] = As[k][tr + i];
#pragma unroll
            for (int j = 0; j < 8; j++) rb[j] = Bs[k][tc + j];
#pragma unroll
            for (int i = 0; i < 8; i++)
#pragma unroll
                for (int j = 0; j < 8; j++)
                    acc[i][j] = fmaf(ra[i], rb[j], acc[i][j]);
        }
        __syncthreads();
    }

#pragma unroll
    for (int i = 0; i < 8; i++) {
        int r = bm + tr + i;
        if (r < M) {
#pragma unroll
            for (int j = 0; j < 8; j++) {
                int c = bn + tc + j;
                float v = acc[i][j];
                if (bias) v += bias[c];
                if (act == 1) v = fmaxf(v, 0.f);
                C[(size_t)r * N + c] = v;
            }
        }
    }
}

// ---------------------------------------------------------------------------
// Per-node attention logits: s_src[n,h] = <h[n,h,:], a_src[h,:]>, same for dst.
// blockDim = H*32, one warp per head.
// ---------------------------------------------------------------------------
template <int H, int C>
__global__ void logits_kernel(const float* __restrict__ hin,
                              const float* __restrict__ a_src,
                              const float* __restrict__ a_dst,
                              float* __restrict__ ss, float* __restrict__ sd) {
    int n = blockIdx.x;
    int warp = threadIdx.x >> 5;
    int lane = threadIdx.x & 31;
    const float* hr = hin + (size_t)n * H * C + warp * C;
    float as_ = 0.f, ad_ = 0.f;
#pragma unroll
    for (int c = lane; c < C; c += 32) {
        float v = hr[c];
        as_ = fmaf(v, a_src[warp * C + c], as_);
        ad_ = fmaf(v, a_dst[warp * C + c], ad_);
    }
#pragma unroll
    for (int o = 16; o; o >>= 1) {
        as_ += __shfl_down_sync(0xFFFFFFFFu, as_, o);
        ad_ += __shfl_down_sync(0xFFFFFFFFu, ad_, o);
    }
    if (lane == 0) {
        ss[n * H + warp] = as_;
        sd[n * H + warp] = ad_;
    }
}

// ---------------------------------------------------------------------------
// Attention: per-dst-node block. Segment softmax (max, exp, sum) over the
// node's incoming CSR edges, then aggregate h[src]*alpha, add bias, ELU.
// blockDim = 256. VPT = H*C/256 features per thread.
// ---------------------------------------------------------------------------
template <int H, int C>
__global__ __launch_bounds__(256)
void attn_kernel(const float* __restrict__ hin,
                 const float* __restrict__ s_src,
                 const float* __restrict__ s_dst,
                 const int* __restrict__ rowptr,
                 const int* __restrict__ csrc,
                 float* __restrict__ alpha,
                 const float* __restrict__ bias,
                 float* __restrict__ out) {
    constexpr int HC = H * C;
    constexpr int VPT = HC / 256;
    int n = blockIdx.x;
    int tid = threadIdx.x;
    int base = rowptr[n];
    int deg = rowptr[n + 1] - base;

    __shared__ unsigned smax[H];
    __shared__ float ssum[H];
    __shared__ float sinv[H];
    if (tid < H) { smax[tid] = 0u; ssum[tid] = 0.f; }
    __syncthreads();

    float sdn[H];
#pragma unroll
    for (int h = 0; h < H; h++) sdn[h] = s_dst[n * H + h];

    int tot = deg * H;
    for (int idx = tid; idx < tot; idx += 256) {
        int j = idx / H, h = idx % H;
        int s = csrc[base + j];
        float v = s_src[s * H + h] + sdn[h];
        v = v > 0.f ? v : 0.2f * v;          // leaky_relu(0.2)
        alpha[(size_t)(base + j) * H + h] = v;
        atomicMax(&smax[h], fenc(v));
    }
    __syncthreads();
    float m[H];
#pragma unroll
    for (int h = 0; h < H; h++) m[h] = fdec(smax[h]);
    for (int idx = tid; idx < tot; idx += 256) {
        int j = idx / H, h = idx % H;
        size_t p = (size_t)(base + j) * H + h;
        float ex = __expf(alpha[p] - m[h]);
        alpha[p] = ex;
        atomicAdd(&ssum[h], ex);
    }
    __syncthreads();
    if (tid < H) sinv[tid] = 1.f / (ssum[tid] + 1e-16f);
    __syncthreads();

    float acc[VPT];
#pragma unroll
    for (int k = 0; k < VPT; k++) acc[k] = 0.f;

    for (int j = 0; j < deg; j++) {
        int s = csrc[base + j];
        const float* hr = hin + (size_t)s * HC;
        if (H == 4) {
            float4 av = *reinterpret_cast<const float4*>(&alpha[(size_t)(base + j) * 4]);
            float a[4] = {av.x, av.y, av.z, av.w};
#pragma unroll
            for (int k = 0; k < VPT; k++)
                acc[k] = fmaf(hr[tid + k * 256], a[(tid + k * 256) / C], acc[k]);
        } else {
            float a = alpha[(size_t)(base + j) * H];
#pragma unroll
            for (int k = 0; k < VPT; k++)
                acc[k] = fmaf(hr[tid + k * 256], a, acc[k]);
        }
    }

#pragma unroll
    for (int k = 0; k < VPT; k++) {
        int f = tid + k * 256;
        int h = f / C;
        float v = acc[k] * sinv[h] + bias[f];
        out[(size_t)n * HC + f] = v > 0.f ? v : expm1f(v);   // ELU
    }
}

// ---------------------------------------------------------------------------
// Mean pool: gf[c] = mean over rows of h[:,c]. gf must be pre-zeroed.
// ---------------------------------------------------------------------------
__global__ void zerof_kernel(float* a, int n) {
    int i = blockIdx.x * 256 + threadIdx.x;
    if (i < n) a[i] = 0.f;
}

__global__ void mean_kernel(const float* __restrict__ h, float* __restrict__ gf, int N) {
    int c = threadIdx.x;            // 256 cols
    int nb = gridDim.x;
    int rows = (N + nb - 1) / nb;
    int r0 = blockIdx.x * rows;
    int r1 = min(r0 + rows, N);
    float s = 0.f;
    for (int r = r0; r < r1; r++) s += h[(size_t)r * 256 + c];
    atomicAdd(&gf[c], s / (float)N);
}

// ---------------------------------------------------------------------------
// Influence head second layer: infl[n] = sigmoid(<t[n,:],Wp2> + bp2).
// One warp per node; t row is 128 floats -> one float4 per lane.
// ---------------------------------------------------------------------------
__global__ void infl_kernel(const float* __restrict__ t, const float* __restrict__ Wp2,
                            const float* __restrict__ bp2, float* __restrict__ infl, int N) {
    int g = blockIdx.x * blockDim.x + threadIdx.x;
    int n = g >> 5;
    int lane = g & 31;
    if (n >= N) return;
    float4 tv = reinterpret_cast<const float4*>(t + (size_t)n * 128)[lane];
    float4 wv = reinterpret_cast<const float4*>(Wp2)[lane];
    float s = tv.x * wv.x + tv.y * wv.y + tv.z * wv.z + tv.w * wv.w;
#pragma unroll
    for (int o = 16; o; o >>= 1) s += __shfl_down_sync(0xFFFFFFFFu, s, o);
    if (lane == 0) infl[n] = 1.f / (1.f + __expf(-(s + bp2[0])));
}

// ---------------------------------------------------------------------------
extern "C" void kernel_launch(void* const* d_in, const int* in_sizes, int n_in,
                              void* d_out, int out_size) {
    const float* x      = (const float*)d_in[0];
    const int*   ei     = (const int*)d_in[1];
    const float* W1     = (const float*)d_in[2];
    const float* a_src1 = (const float*)d_in[3];
    const float* a_dst1 = (const float*)d_in[4];
    const float* b1     = (const float*)d_in[5];
    const float* W2     = (const float*)d_in[6];
    const float* a_src2 = (const float*)d_in[7];
    const float* a_dst2 = (const float*)d_in[8];
    const float* b2     = (const float*)d_in[9];
    const float* Wp1    = (const float*)d_in[10];
    const float* bp1    = (const float*)d_in[11];
    const float* Wp2    = (const float*)d_in[12];
    const float* bp2    = (const float*)d_in[13];

    int N = in_sizes[0] / 384;
    int E = in_sizes[1] / 2;
    int Etot = E + N;

    float *h1, *h1p, *h2, *t, *alpha, *ss, *sd;
    int *deg, *cnt, *rowptr, *csrc;
    cudaGetSymbolAddress((void**)&h1, g_h1);
    cudaGetSymbolAddress((void**)&h1p, g_h1p);
    cudaGetSymbolAddress((void**)&h2, g_h2);
    cudaGetSymbolAddress((void**)&t, g_t);
    cudaGetSymbolAddress((void**)&alpha, g_alpha);
    cudaGetSymbolAddress((void**)&ss, g_ss);
    cudaGetSymbolAddress((void**)&sd, g_sd);
    cudaGetSymbolAddress((void**)&deg, g_deg);
    cudaGetSymbolAddress((void**)&cnt, g_cnt);
    cudaGetSymbolAddress((void**)&rowptr, g_rowptr);
    cudaGetSymbolAddress((void**)&csrc, g_csrc);

    float* out_h  = (float*)d_out;                 // [N,256]
    float* out_gf = out_h + (size_t)N * 256;       // [256]
    float* out_in = out_gf + 256;                  // [N]

    int eb = (Etot + 255) / 256;
    int nb = (N + 255) / 256;

    // CSR build
    zero2_kernel<<<nb, 256>>>(deg, cnt, N);
    hist_kernel<<<eb, 256>>>(ei + E, E, N, deg);
    scan_kernel<<<1, 1024>>>(deg, rowptr, N, Etot);
    scatter_kernel<<<eb, 256>>>(ei, ei + E, E, N, rowptr, cnt, csrc);

    int mtiles = (N + 127) / 128;

    // Layer 1
    {
        dim3 g(1024 / 128, mtiles);
        sgemm_kernel<<<g, 256>>>(x, W1, h1, N, 1024, 384, nullptr, 0);
    }
    logits_kernel<4, 256><<<N, 128>>>(h1, a_src1, a_dst1, ss, sd);
    attn_kernel<4, 256><<<N, 256>>>(h1, ss, sd, rowptr, csrc, alpha, b1, h1p);

    // Layer 2
    {
        dim3 g(256 / 128, mtiles);
        sgemm_kernel<<<g, 256>>>(h1p, W2, h2, N, 256, 1024, nullptr, 0);
    }
    logits_kernel<1, 256><<<N, 32>>>(h2, a_src2, a_dst2, ss, sd);
    attn_kernel<1, 256><<<N, 256>>>(h2, ss, sd, rowptr, csrc, alpha, b2, out_h);

    // Graph mean pool
    zerof_kernel<<<1, 256>>>(out_gf, 256);
    mean_kernel<<<128, 256>>>(out_h, out_gf, N);

    // Influence MLP
    {
        dim3 g(128 / 128, mtiles);
        sgemm_kernel<<<g, 256>>>(out_h, Wp1, t, N, 128, 256, bp1, 1);
    }
    infl_kernel<<<(N * 32 + 255) / 256, 256>>>(t, Wp2, bp2, out_in, N);
}

// round 3
// speedup vs baseline: 1.6625x; 1.6625x over previous
#include <cuda_runtime.h>
#include <cuda_bf16.h>
#include <math.h>
#include <stdint.h>

// ===========================================================================
// GraphAttentionInfluence on GB300 (compiled as baseline compute_103):
//   GEMMs via mma.sync bf16 HMMA with 3-term hi/lo split (~fp32 precision),
//   cp.async double-buffered tiles; attention segment-softmax per dst node.
// ===========================================================================

#define N_MAX   20480
#define E_MAX   327680
#define ETOT_MAX (N_MAX + E_MAX)

__device__ float g_h1 [(size_t)N_MAX * 1024];
__device__ float g_t  [(size_t)N_MAX * 128];
__device__ __nv_bfloat16 g_xh [(size_t)N_MAX * 384];
__device__ __nv_bfloat16 g_xl [(size_t)N_MAX * 384];
__device__ __nv_bfloat16 g_h1ph[(size_t)N_MAX * 1024];
__device__ __nv_bfloat16 g_h1pl[(size_t)N_MAX * 1024];
__device__ __nv_bfloat16 g_hh [(size_t)N_MAX * 256];
__device__ __nv_bfloat16 g_hl [(size_t)N_MAX * 256];
__device__ float g_h2 [(size_t)N_MAX * 256];
__device__ __nv_bfloat16 g_w1h[1024 * 384], g_w1l[1024 * 384];
__device__ __nv_bfloat16 g_w2h[256 * 1024], g_w2l[256 * 1024];
__device__ __nv_bfloat16 g_wph[128 * 256],  g_wpl[128 * 256];
__device__ float g_alpha[(size_t)ETOT_MAX * 4];
__device__ float g_ss[N_MAX * 4];
__device__ float g_sd[N_MAX * 4];
__device__ int   g_deg[N_MAX];
__device__ int   g_cnt[N_MAX];
__device__ int   g_rowptr[N_MAX + 1];
__device__ int   g_csrc[ETOT_MAX];

// ---------------------------------------------------------------------------
__device__ __forceinline__ uint32_t smem_u32(const void* p) {
    uint32_t a;
    asm("{ .reg .u64 t; cvta.to.shared.u64 t, %1; cvt.u32.u64 %0, t; }" : "=r"(a) : "l"(p));
    return a;
}
__device__ __forceinline__ void ldsm4(uint32_t& r0, uint32_t& r1, uint32_t& r2, uint32_t& r3,
                                      uint32_t addr) {
    asm volatile("ldmatrix.sync.aligned.m8n8.x4.shared.b16 {%0,%1,%2,%3}, [%4];"
                 : "=r"(r0), "=r"(r1), "=r"(r2), "=r"(r3) : "r"(addr));
}
__device__ __forceinline__ void mma16816(float* d, const uint32_t* a, const uint32_t* b) {
    asm volatile(
        "mma.sync.aligned.m16n8k16.row.col.f32.bf16.bf16.f32 "
        "{%0,%1,%2,%3}, {%4,%5,%6,%7}, {%8,%9}, {%0,%1,%2,%3};"
        : "+f"(d[0]), "+f"(d[1]), "+f"(d[2]), "+f"(d[3])
        : "r"(a[0]), "r"(a[1]), "r"(a[2]), "r"(a[3]), "r"(b[0]), "r"(b[1]));
}
__device__ __forceinline__ void cp16(uint32_t dst, const void* src, int ok) {
    asm volatile("cp.async.cg.shared.global [%0], [%1], 16, %2;"
                 :: "r"(dst), "l"(src), "r"(ok ? 16 : 0));
}
#define CP_COMMIT() asm volatile("cp.async.commit_group;" ::: "memory")
#define CP_WAIT1()  asm volatile("cp.async.wait_group 1;" ::: "memory")
#define CP_WAIT0()  asm volatile("cp.async.wait_group 0;" ::: "memory")

__device__ __forceinline__ void split2(float v, __nv_bfloat16& hi, __nv_bfloat16& lo) {
    hi = __float2bfloat16(v);
    lo = __float2bfloat16(v - __bfloat162float(hi));
}

// ---------------------------------------------------------------------------
// HMMA GEMM: C[M,Ntot] = A[M,K] @ B[Ntot,K]^T (both K-major, hi/lo pairs).
// Block 128x128, BK=32, 8 warps, cp.async double-buffer.
// Smem stage: Ahi|Alo|Bhi|Blo, each 128 rows x 80B (32 bf16 + 8 pad).
// ---------------------------------------------------------------------------
__global__ __launch_bounds__(256, 1)
void hmma_gemm_kernel(const __nv_bfloat16* __restrict__ Ahi, const __nv_bfloat16* __restrict__ Alo,
                      const __nv_bfloat16* __restrict__ Bhi, const __nv_bfloat16* __restrict__ Blo,
                      float* __restrict__ C, int M, int Ntot, int K,
                      const float* __restrict__ bias, int act) {
    extern __shared__ __align__(128) char smem[];
    constexpr int RS = 80;            // row stride bytes
    constexpr int HALF = 128 * RS;    // 10240 per operand-half
    constexpr int STG = 4 * HALF;     // 40960 per stage

    const int tid = threadIdx.x;
    const int wid = tid >> 5, lane = tid & 31;
    const int wm = wid & 3, wn = wid >> 2;
    const int bm = blockIdx.y * 128, bn = blockIdx.x * 128;
    const int grp = lane >> 3, r8 = lane & 7;
    uint32_t sb = smem_u32(smem);

    // per-thread cp.async chunk coords: 2 chunks per half per thread
    int c0 = tid, c1 = tid + 256;

    const __nv_bfloat16* bases[4] = {Ahi, Alo, Bhi, Blo};

    auto gload = [&](uint32_t stage_off, int k0) {
#pragma unroll
        for (int h = 0; h < 4; h++) {
#pragma unroll
            for (int rep = 0; rep < 2; rep++) {
                int c = rep ? c1 : c0;
                int row = c >> 2, q = c & 3;
                int grow = (h < 2 ? bm : bn) + row;
                int ok = (h < 2) ? (grow < M) : 1;
                const __nv_bfloat16* src = bases[h] + (size_t)grow * K + k0 + q * 8;
                cp16(sb + stage_off + h * HALF + row * RS + q * 16, src, ok);
            }
        }
    };

    float acc[2][8][4];
#pragma unroll
    for (int i = 0; i < 2; i++)
#pragma unroll
        for (int j = 0; j < 8; j++)
#pragma unroll
            for (int q = 0; q < 4; q++) acc[i][j][q] = 0.f;

    // ldmatrix relative offsets (within stage)
    uint32_t a_off[2], b_off[4];
#pragma unroll
    for (int i = 0; i < 2; i++)
        a_off[i] = (uint32_t)((wm * 32 + i * 16 + (grp & 1) * 8 + r8) * RS);
#pragma unroll
    for (int jp = 0; jp < 4; jp++)
        b_off[jp] = (uint32_t)(2 * HALF + (wn * 64 + jp * 16 + (grp >> 1) * 8 + r8) * RS);

    int nk = K >> 5;
    gload(0, 0);   CP_COMMIT();
    gload(STG, 32); CP_COMMIT();

    for (int it = 0; it < nk; it++) {
        if (it + 1 < nk) CP_WAIT1(); else CP_WAIT0();
        __syncthreads();
        uint32_t sbase = sb + (uint32_t)(it & 1) * STG;

#pragma unroll
        for (int ks = 0; ks < 2; ks++) {
            uint32_t ka = (uint32_t)((ks * 16 + (grp >> 1) * 8) * 2);
            uint32_t kbq = (uint32_t)((ks * 16 + (grp & 1) * 8) * 2);
            uint32_t ahr[2][4], alr[2][4], bhr[4][4], blr[4][4];
#pragma unroll
            for (int i = 0; i < 2; i++) {
                ldsm4(ahr[i][0], ahr[i][1], ahr[i][2], ahr[i][3], sbase + a_off[i] + ka);
                ldsm4(alr[i][0], alr[i][1], alr[i][2], alr[i][3], sbase + HALF + a_off[i] + ka);
            }
#pragma unroll
            for (int jp = 0; jp < 4; jp++) {
                ldsm4(bhr[jp][0], bhr[jp][1], bhr[jp][2], bhr[jp][3], sbase + b_off[jp] + kbq);
                ldsm4(blr[jp][0], blr[jp][1], blr[jp][2], blr[jp][3], sbase + HALF + b_off[jp] + kbq);
            }
            // term 1: Ahi * Bhi
#pragma unroll
            for (int i = 0; i < 2; i++)
#pragma unroll
                for (int j = 0; j < 8; j++)
                    mma16816(acc[i][j], ahr[i], &bhr[j >> 1][(j & 1) * 2]);
            // term 2: Ahi * Blo
#pragma unroll
            for (int i = 0; i < 2; i++)
#pragma unroll
                for (int j = 0; j < 8; j++)
                    mma16816(acc[i][j], ahr[i], &blr[j >> 1][(j & 1) * 2]);
            // term 3: Alo * Bhi
#pragma unroll
            for (int i = 0; i < 2; i++)
#pragma unroll
                for (int j = 0; j < 8; j++)
                    mma16816(acc[i][j], alr[i], &bhr[j >> 1][(j & 1) * 2]);
        }
        __syncthreads();
        if (it + 2 < nk) { gload((uint32_t)(it & 1) * STG, (it + 2) * 32); CP_COMMIT(); }
    }

    // epilogue
#pragma unroll
    for (int i = 0; i < 2; i++) {
        int row0 = bm + wm * 32 + i * 16 + (lane >> 2);
#pragma unroll
        for (int hf = 0; hf < 2; hf++) {
            int row = row0 + hf * 8;
            if (row < M) {
#pragma unroll
                for (int j = 0; j < 8; j++) {
                    int col = bn + wn * 64 + j * 8 + (lane & 3) * 2;
                    float v0 = acc[i][j][hf * 2 + 0];
                    float v1 = acc[i][j][hf * 2 + 1];
                    if (bias) { v0 += bias[col]; v1 += bias[col + 1]; }
                    if (act) { v0 = fmaxf(v0, 0.f); v1 = fmaxf(v1, 0.f); }
                    *reinterpret_cast<float2*>(C + (size_t)row * Ntot + col) = make_float2(v0, v1);
                }
            }
        }
    }
}

// ---------------------------------------------------------------------------
// operand prep
// ---------------------------------------------------------------------------
__global__ void split_kernel(const float* __restrict__ in, __nv_bfloat16* __restrict__ hi,
                             __nv_bfloat16* __restrict__ lo, int n) {
    int i = blockIdx.x * 256 + threadIdx.x;
    if (i < n) { __nv_bfloat16 h, l; split2(in[i], h, l); hi[i] = h; lo[i] = l; }
}
__global__ void tsplit_kernel(const float* __restrict__ W, int K, int Nn,
                              __nv_bfloat16* __restrict__ hi, __nv_bfloat16* __restrict__ lo) {
    int i = blockIdx.x * 256 + threadIdx.x;
    if (i < Nn * K) {
        int n = i / K, k = i - n * K;
        __nv_bfloat16 h, l; split2(W[(size_t)k * Nn + n], h, l);
        hi[i] = h; lo[i] = l;
    }
}

// ---------------------------------------------------------------------------
// CSR build
// ---------------------------------------------------------------------------
__global__ void zero2_kernel(int* a, int* b, int n) {
    int i = blockIdx.x * 256 + threadIdx.x;
    if (i < n) { a[i] = 0; b[i] = 0; }
}
__global__ void hist_kernel(const int* __restrict__ dst, int E, int N, int* __restrict__ deg) {
    int e = blockIdx.x * 256 + threadIdx.x;
    if (e < E + N) atomicAdd(&deg[(e < E) ? dst[e] : (e - E)], 1);
}
__global__ void scan_kernel(const int* __restrict__ deg, int* __restrict__ rowptr, int N, int Etot) {
    __shared__ int part[1024];
    int tid = threadIdx.x;
    int chunk = (N + 1023) >> 10;
    int lo = tid * chunk, hi = min(lo + chunk, N);
    int s = 0;
    for (int i = lo; i < hi; i++) s += deg[i];
    part[tid] = s; __syncthreads();
    for (int off = 1; off < 1024; off <<= 1) {
        int v = (tid >= off) ? part[tid - off] : 0;
        __syncthreads(); part[tid] += v; __syncthreads();
    }
    int run = tid ? part[tid - 1] : 0;
    for (int i = lo; i < hi; i++) { rowptr[i] = run; run += deg[i]; }
    if (tid == 0) rowptr[N] = Etot;
}
__global__ void scatter_kernel(const int* __restrict__ src, const int* __restrict__ dst,
                               int E, int N, const int* __restrict__ rowptr,
                               int* __restrict__ cnt, int* __restrict__ csrc) {
    int e = blockIdx.x * 256 + threadIdx.x;
    if (e < E + N) {
        int d, s;
        if (e < E) { d = dst[e]; s = src[e]; } else { d = e - E; s = e - E; }
        csrc[rowptr[d] + atomicAdd(&cnt[d], 1)] = s;
    }
}

// ---------------------------------------------------------------------------
// attention logits
// ---------------------------------------------------------------------------
template <int H, int C>
__global__ void logits_kernel(const float* __restrict__ hin,
                              const float* __restrict__ a_src, const float* __restrict__ a_dst,
                              float* __restrict__ ss, float* __restrict__ sd) {
    int n = blockIdx.x;
    int warp = threadIdx.x >> 5, lane = threadIdx.x & 31;
    const float* hr = hin + (size_t)n * H * C + warp * C;
    float as_ = 0.f, ad_ = 0.f;
#pragma unroll
    for (int c = lane; c < C; c += 32) {
        float v = hr[c];
        as_ = fmaf(v, a_src[warp * C + c], as_);
        ad_ = fmaf(v, a_dst[warp * C + c], ad_);
    }
#pragma unroll
    for (int o = 16; o; o >>= 1) {
        as_ += __shfl_down_sync(0xFFFFFFFFu, as_, o);
        ad_ += __shfl_down_sync(0xFFFFFFFFu, ad_, o);
    }
    if (lane == 0) { ss[n * H + warp] = as_; sd[n * H + warp] = ad_; }
}

// ---------------------------------------------------------------------------
// attention + ELU, optional fp32 out and fused hi/lo bf16 out
// ---------------------------------------------------------------------------
__device__ __forceinline__ unsigned fenc(float f) {
    unsigned u = __float_as_uint(f);
    return (u >> 31) ? ~u : (u | 0x80000000u);
}
__device__ __forceinline__ float fdec(unsigned u) {
    return (u >> 31) ? __uint_as_float(u & 0x7FFFFFFFu) : __uint_as_float(~u);
}

template <int H, int C>
__global__ __launch_bounds__(256)
void attn_kernel(const float* __restrict__ hin,
                 const float* __restrict__ s_src, const float* __restrict__ s_dst,
                 const int* __restrict__ rowptr, const int* __restrict__ csrc,
                 float* __restrict__ alpha, const float* __restrict__ bias,
                 float* __restrict__ out,
                 __nv_bfloat16* __restrict__ outhi, __nv_bfloat16* __restrict__ outlo) {
    constexpr int HC = H * C;
    constexpr int VPT = HC / 256;
    int n = blockIdx.x, tid = threadIdx.x;
    int base = rowptr[n];
    int deg = rowptr[n + 1] - base;

    __shared__ unsigned smax[H];
    __shared__ float ssum[H], sinv[H];
    if (tid < H) { smax[tid] = 0u; ssum[tid] = 0.f; }
    __syncthreads();

    float sdn[H];
#pragma unroll
    for (int h = 0; h < H; h++) sdn[h] = s_dst[n * H + h];

    int tot = deg * H;
    for (int idx = tid; idx < tot; idx += 256) {
        int j = idx / H, h = idx % H;
        int s = csrc[base + j];
        float v = s_src[s * H + h] + sdn[h];
        v = v > 0.f ? v : 0.2f * v;
        alpha[(size_t)(base + j) * H + h] = v;
        atomicMax(&smax[h], fenc(v));
    }
    __syncthreads();
    float m[H];
#pragma unroll
    for (int h = 0; h < H; h++) m[h] = fdec(smax[h]);
    for (int idx = tid; idx < tot; idx += 256) {
        int j = idx / H, h = idx % H;
        size_t p = (size_t)(base + j) * H + h;
        float ex = __expf(alpha[p] - m[h]);
        alpha[p] = ex;
        atomicAdd(&ssum[h], ex);
    }
    __syncthreads();
    if (tid < H) sinv[tid] = 1.f / (ssum[tid] + 1e-16f);
    __syncthreads();

    float acc[VPT];
#pragma unroll
    for (int k = 0; k < VPT; k++) acc[k] = 0.f;

    for (int j = 0; j < deg; j++) {
        int s = csrc[base + j];
        const float* hr = hin + (size_t)s * HC;
        if (H == 4) {
            float4 av = *reinterpret_cast<const float4*>(&alpha[(size_t)(base + j) * 4]);
            float a[4] = {av.x, av.y, av.z, av.w};
#pragma unroll
            for (int k = 0; k < VPT; k++)
                acc[k] = fmaf(hr[tid + k * 256], a[(tid + k * 256) / C], acc[k]);
        } else {
            float a = alpha[(size_t)(base + j) * H];
#pragma unroll
            for (int k = 0; k < VPT; k++)
                acc[k] = fmaf(hr[tid + k * 256], a, acc[k]);
        }
    }

#pragma unroll
    for (int k = 0; k < VPT; k++) {
        int f = tid + k * 256;
        int h = f / C;
        float v = acc[k] * sinv[h] + bias[f];
        v = v > 0.f ? v : expm1f(v);
        if (out) out[(size_t)n * HC + f] = v;
        if (outhi) {
            __nv_bfloat16 bh, bl; split2(v, bh, bl);
            outhi[(size_t)n * HC + f] = bh;
            outlo[(size_t)n * HC + f] = bl;
        }
    }
}

// ---------------------------------------------------------------------------
// mean pool + influence head
// ---------------------------------------------------------------------------
__global__ void zerof_kernel(float* a, int n) {
    int i = blockIdx.x * 256 + threadIdx.x;
    if (i < n) a[i] = 0.f;
}
__global__ void mean_kernel(const float* __restrict__ h, float* __restrict__ gf, int N) {
    int c = threadIdx.x;
    int rows = (N + gridDim.x - 1) / gridDim.x;
    int r0 = blockIdx.x * rows, r1 = min(r0 + rows, N);
    float s = 0.f;
    for (int r = r0; r < r1; r++) s += h[(size_t)r * 256 + c];
    atomicAdd(&gf[c], s / (float)N);
}
__global__ void infl_kernel(const float* __restrict__ t, const float* __restrict__ Wp2,
                            const float* __restrict__ bp2, float* __restrict__ infl, int N) {
    int g = blockIdx.x * blockDim.x + threadIdx.x;
    int n = g >> 5, lane = g & 31;
    if (n >= N) return;
    float4 tv = reinterpret_cast<const float4*>(t + (size_t)n * 128)[lane];
    float4 wv = reinterpret_cast<const float4*>(Wp2)[lane];
    float s = tv.x * wv.x + tv.y * wv.y + tv.z * wv.z + tv.w * wv.w;
#pragma unroll
    for (int o = 16; o; o >>= 1) s += __shfl_down_sync(0xFFFFFFFFu, s, o);
    if (lane == 0) infl[n] = 1.f / (1.f + __expf(-(s + bp2[0])));
}

// ---------------------------------------------------------------------------
extern "C" void kernel_launch(void* const* d_in, const int* in_sizes, int n_in,
                              void* d_out, int out_size) {
    const float* x      = (const float*)d_in[0];
    const int*   ei     = (const int*)d_in[1];
    const float* W1     = (const float*)d_in[2];
    const float* a_src1 = (const float*)d_in[3];
    const float* a_dst1 = (const float*)d_in[4];
    const float* b1     = (const float*)d_in[5];
    const float* W2     = (const float*)d_in[6];
    const float* a_src2 = (const float*)d_in[7];
    const float* a_dst2 = (const float*)d_in[8];
    const float* b2     = (const float*)d_in[9];
    const float* Wp1    = (const float*)d_in[10];
    const float* bp1    = (const float*)d_in[11];
    const float* Wp2    = (const float*)d_in[12];
    const float* bp2    = (const float*)d_in[13];

    int N = in_sizes[0] / 384;
    int E = in_sizes[1] / 2;
    int Etot = E + N;

    float *h1, *h2, *t, *alpha, *ss, *sd;
    __nv_bfloat16 *xh, *xl, *h1ph, *h1pl, *hh, *hl, *w1h, *w1l, *w2h, *w2l, *wph, *wpl;
    int *deg, *cnt, *rowptr, *csrc;
    cudaGetSymbolAddress((void**)&h1, g_h1);
    cudaGetSymbolAddress((void**)&h2, g_h2);
    cudaGetSymbolAddress((void**)&t, g_t);
    cudaGetSymbolAddress((void**)&alpha, g_alpha);
    cudaGetSymbolAddress((void**)&ss, g_ss);
    cudaGetSymbolAddress((void**)&sd, g_sd);
    cudaGetSymbolAddress((void**)&xh, g_xh);
    cudaGetSymbolAddress((void**)&xl, g_xl);
    cudaGetSymbolAddress((void**)&h1ph, g_h1ph);
    cudaGetSymbolAddress((void**)&h1pl, g_h1pl);
    cudaGetSymbolAddress((void**)&hh, g_hh);
    cudaGetSymbolAddress((void**)&hl, g_hl);
    cudaGetSymbolAddress((void**)&w1h, g_w1h);
    cudaGetSymbolAddress((void**)&w1l, g_w1l);
    cudaGetSymbolAddress((void**)&w2h, g_w2h);
    cudaGetSymbolAddress((void**)&w2l, g_w2l);
    cudaGetSymbolAddress((void**)&wph, g_wph);
    cudaGetSymbolAddress((void**)&wpl, g_wpl);
    cudaGetSymbolAddress((void**)&deg, g_deg);
    cudaGetSymbolAddress((void**)&cnt, g_cnt);
    cudaGetSymbolAddress((void**)&rowptr, g_rowptr);
    cudaGetSymbolAddress((void**)&csrc, g_csrc);

    float* out_h  = (float*)d_out;
    float* out_gf = out_h + (size_t)N * 256;
    float* out_in = out_gf + 256;

    cudaFuncSetAttribute(hmma_gemm_kernel, cudaFuncAttributeMaxDynamicSharedMemorySize, 81920);

    int eb = (Etot + 255) / 256;
    int nb = (N + 255) / 256;
    int mtiles = (N + 127) / 128;

    // operand prep
    split_kernel<<<(N * 384 + 255) / 256, 256>>>(x, xh, xl, N * 384);
    tsplit_kernel<<<(1024 * 384 + 255) / 256, 256>>>(W1, 384, 1024, w1h, w1l);
    tsplit_kernel<<<(256 * 1024 + 255) / 256, 256>>>(W2, 1024, 256, w2h, w2l);
    tsplit_kernel<<<(128 * 256 + 255) / 256, 256>>>(Wp1, 256, 128, wph, wpl);

    // CSR build
    zero2_kernel<<<nb, 256>>>(deg, cnt, N);
    hist_kernel<<<eb, 256>>>(ei + E, E, N, deg);
    scan_kernel<<<1, 1024>>>(deg, rowptr, N, Etot);
    scatter_kernel<<<eb, 256>>>(ei, ei + E, E, N, rowptr, cnt, csrc);

    // Layer 1: h1 = x @ W1  [N,1024], K=384
    {
        dim3 g(1024 / 128, mtiles);
        hmma_gemm_kernel<<<g, 256, 81920>>>(xh, xl, w1h, w1l, h1, N, 1024, 384, nullptr, 0);
    }
    logits_kernel<4, 256><<<N, 128>>>(h1, a_src1, a_dst1, ss, sd);
    attn_kernel<4, 256><<<N, 256>>>(h1, ss, sd, rowptr, csrc, alpha, b1, nullptr, h1ph, h1pl);

    // Layer 2: h2 = h1p @ W2  [N,256], K=1024
    {
        dim3 g(256 / 128, mtiles);
        hmma_gemm_kernel<<<g, 256, 81920>>>(h1ph, h1pl, w2h, w2l, h2, N, 256, 1024, nullptr, 0);
    }
    logits_kernel<1, 256><<<N, 32>>>(h2, a_src2, a_dst2, ss, sd);
    attn_kernel<1, 256><<<N, 256>>>(h2, ss, sd, rowptr, csrc, alpha, b2, out_h, hh, hl);

    // pooling
    zerof_kernel<<<1, 256>>>(out_gf, 256);
    mean_kernel<<<128, 256>>>(out_h, out_gf, N);

    // influence MLP: t = relu(h @ Wp1 + bp1)  [N,128], K=256
    {
        dim3 g(128 / 128, mtiles);
        hmma_gemm_kernel<<<g, 256, 81920>>>(hh, hl, wph, wpl, t, N, 128, 256, bp1, 1);
    }
    infl_kernel<<<(N * 32 + 255) / 256, 256>>>(t, Wp2, bp2, out_in, N);
}

// round 4
// speedup vs baseline: 1.9440x; 1.1693x over previous
#include <cuda_runtime.h>
#include <cuda_bf16.h>
#include <math.h>
#include <stdint.h>

// ===========================================================================
// GraphAttentionInfluence on GB300 (baseline compute_103 target):
//   GEMMs: mma.sync bf16 HMMA, 3-term hi/lo split, 3-stage cp.async pipeline
//   attention: per-dst-node segment softmax, float4-vectorized aggregation
// ===========================================================================

#define N_MAX   20480
#define E_MAX   327680
#define ETOT_MAX (N_MAX + E_MAX)

__device__ float g_h1 [(size_t)N_MAX * 1024];
__device__ float g_t  [(size_t)N_MAX * 128];
__device__ __nv_bfloat16 g_xh [(size_t)N_MAX * 384];
__device__ __nv_bfloat16 g_xl [(size_t)N_MAX * 384];
__device__ __nv_bfloat16 g_h1ph[(size_t)N_MAX * 1024];
__device__ __nv_bfloat16 g_h1pl[(size_t)N_MAX * 1024];
__device__ __nv_bfloat16 g_hh [(size_t)N_MAX * 256];
__device__ __nv_bfloat16 g_hl [(size_t)N_MAX * 256];
__device__ float g_h2 [(size_t)N_MAX * 256];
__device__ __nv_bfloat16 g_w1h[1024 * 384], g_w1l[1024 * 384];
__device__ __nv_bfloat16 g_w2h[256 * 1024], g_w2l[256 * 1024];
__device__ __nv_bfloat16 g_wph[128 * 256],  g_wpl[128 * 256];
__device__ float g_alpha[(size_t)ETOT_MAX * 4];
__device__ float g_ss[N_MAX * 4];
__device__ float g_sd[N_MAX * 4];
__device__ int   g_deg[N_MAX];
__device__ int   g_cnt[N_MAX];
__device__ int   g_rowptr[N_MAX + 1];
__device__ int   g_csrc[ETOT_MAX];

// ---------------------------------------------------------------------------
__device__ __forceinline__ uint32_t smem_u32(const void* p) {
    uint32_t a;
    asm("{ .reg .u64 t; cvta.to.shared.u64 t, %1; cvt.u32.u64 %0, t; }" : "=r"(a) : "l"(p));
    return a;
}
__device__ __forceinline__ void ldsm4(uint32_t& r0, uint32_t& r1, uint32_t& r2, uint32_t& r3,
                                      uint32_t addr) {
    asm volatile("ldmatrix.sync.aligned.m8n8.x4.shared.b16 {%0,%1,%2,%3}, [%4];"
                 : "=r"(r0), "=r"(r1), "=r"(r2), "=r"(r3) : "r"(addr));
}
__device__ __forceinline__ void mma16816(float* d, const uint32_t* a, const uint32_t* b) {
    asm volatile(
        "mma.sync.aligned.m16n8k16.row.col.f32.bf16.bf16.f32 "
        "{%0,%1,%2,%3}, {%4,%5,%6,%7}, {%8,%9}, {%0,%1,%2,%3};"
        : "+f"(d[0]), "+f"(d[1]), "+f"(d[2]), "+f"(d[3])
        : "r"(a[0]), "r"(a[1]), "r"(a[2]), "r"(a[3]), "r"(b[0]), "r"(b[1]));
}
__device__ __forceinline__ void cp16(uint32_t dst, const void* src, int ok) {
    asm volatile("cp.async.cg.shared.global [%0], [%1], 16, %2;"
                 :: "r"(dst), "l"(src), "r"(ok ? 16 : 0));
}
#define CP_COMMIT() asm volatile("cp.async.commit_group;" ::: "memory")
#define CP_WAIT1()  asm volatile("cp.async.wait_group 1;" ::: "memory")
#define CP_WAIT0()  asm volatile("cp.async.wait_group 0;" ::: "memory")

__device__ __forceinline__ void split2(float v, __nv_bfloat16& hi, __nv_bfloat16& lo) {
    hi = __float2bfloat16(v);
    lo = __float2bfloat16(v - __bfloat162float(hi));
}

// ---------------------------------------------------------------------------
// HMMA GEMM: C[M,Ntot] = A[M,K] @ B[Ntot,K]^T, hi/lo pairs, 3-term split.
// Block 128x128, BK=32, 8 warps, 3-stage cp.async pipeline.
// ---------------------------------------------------------------------------
__global__ __launch_bounds__(256, 1)
void hmma_gemm_kernel(const __nv_bfloat16* __restrict__ Ahi, const __nv_bfloat16* __restrict__ Alo,
                      const __nv_bfloat16* __restrict__ Bhi, const __nv_bfloat16* __restrict__ Blo,
                      float* __restrict__ C, int M, int Ntot, int K,
                      const float* __restrict__ bias, int act) {
    extern __shared__ __align__(128) char smem[];
    constexpr int RS = 80;
    constexpr int HALF = 128 * RS;
    constexpr int STG = 4 * HALF;     // 40960 per stage

    const int tid = threadIdx.x;
    const int wid = tid >> 5, lane = tid & 31;
    const int wm = wid & 3, wn = wid >> 2;
    const int bm = blockIdx.y * 128, bn = blockIdx.x * 128;
    const int grp = lane >> 3, r8 = lane & 7;
    uint32_t sb = smem_u32(smem);

    int c0 = tid, c1 = tid + 256;
    const __nv_bfloat16* bases[4] = {Ahi, Alo, Bhi, Blo};

    auto gload = [&](int slot, int k0) {
        uint32_t stage_off = (uint32_t)slot * STG;
#pragma unroll
        for (int h = 0; h < 4; h++) {
#pragma unroll
            for (int rep = 0; rep < 2; rep++) {
                int c = rep ? c1 : c0;
                int row = c >> 2, q = c & 3;
                int grow = (h < 2 ? bm : bn) + row;
                int ok = (h < 2) ? (grow < M) : 1;
                const __nv_bfloat16* src = bases[h] + (size_t)grow * K + k0 + q * 8;
                cp16(sb + stage_off + h * HALF + row * RS + q * 16, src, ok);
            }
        }
    };

    float acc[2][8][4];
#pragma unroll
    for (int i = 0; i < 2; i++)
#pragma unroll
        for (int j = 0; j < 8; j++)
#pragma unroll
            for (int q = 0; q < 4; q++) acc[i][j][q] = 0.f;

    uint32_t a_off[2], b_off[4];
#pragma unroll
    for (int i = 0; i < 2; i++)
        a_off[i] = (uint32_t)((wm * 32 + i * 16 + (grp & 1) * 8 + r8) * RS);
#pragma unroll
    for (int jp = 0; jp < 4; jp++)
        b_off[jp] = (uint32_t)(2 * HALF + (wn * 64 + jp * 16 + (grp >> 1) * 8 + r8) * RS);

    int nk = K >> 5;
    gload(0, 0); CP_COMMIT();
    if (nk > 1) { gload(1, 32); CP_COMMIT(); }

    for (int it = 0; it < nk; it++) {
        if (it + 2 <= nk) CP_WAIT1(); else CP_WAIT0();
        __syncthreads();
        uint32_t sbase = sb + (uint32_t)(it % 3) * STG;

#pragma unroll
        for (int ks = 0; ks < 2; ks++) {
            uint32_t ka = (uint32_t)((ks * 16 + (grp >> 1) * 8) * 2);
            uint32_t kbq = (uint32_t)((ks * 16 + (grp & 1) * 8) * 2);
            uint32_t ahr[2][4], alr[2][4], bhr[4][4], blr[4][4];
#pragma unroll
            for (int i = 0; i < 2; i++) {
                ldsm4(ahr[i][0], ahr[i][1], ahr[i][2], ahr[i][3], sbase + a_off[i] + ka);
                ldsm4(alr[i][0], alr[i][1], alr[i][2], alr[i][3], sbase + HALF + a_off[i] + ka);
            }
#pragma unroll
            for (int jp = 0; jp < 4; jp++) {
                ldsm4(bhr[jp][0], bhr[jp][1], bhr[jp][2], bhr[jp][3], sbase + b_off[jp] + kbq);
                ldsm4(blr[jp][0], blr[jp][1], blr[jp][2], blr[jp][3], sbase + HALF + b_off[jp] + kbq);
            }
#pragma unroll
            for (int i = 0; i < 2; i++)
#pragma unroll
                for (int j = 0; j < 8; j++)
                    mma16816(acc[i][j], ahr[i], &bhr[j >> 1][(j & 1) * 2]);
#pragma unroll
            for (int i = 0; i < 2; i++)
#pragma unroll
                for (int j = 0; j < 8; j++)
                    mma16816(acc[i][j], ahr[i], &blr[j >> 1][(j & 1) * 2]);
#pragma unroll
            for (int i = 0; i < 2; i++)
#pragma unroll
                for (int j = 0; j < 8; j++)
                    mma16816(acc[i][j], alr[i], &bhr[j >> 1][(j & 1) * 2]);
        }
        if (it + 2 < nk) { gload((it + 2) % 3, (it + 2) * 32); CP_COMMIT(); }
    }

#pragma unroll
    for (int i = 0; i < 2; i++) {
        int row0 = bm + wm * 32 + i * 16 + (lane >> 2);
#pragma unroll
        for (int hf = 0; hf < 2; hf++) {
            int row = row0 + hf * 8;
            if (row < M) {
#pragma unroll
                for (int j = 0; j < 8; j++) {
                    int col = bn + wn * 64 + j * 8 + (lane & 3) * 2;
                    float v0 = acc[i][j][hf * 2 + 0];
                    float v1 = acc[i][j][hf * 2 + 1];
                    if (bias) { v0 += bias[col]; v1 += bias[col + 1]; }
                    if (act) { v0 = fmaxf(v0, 0.f); v1 = fmaxf(v1, 0.f); }
                    *reinterpret_cast<float2*>(C + (size_t)row * Ntot + col) = make_float2(v0, v1);
                }
            }
        }
    }
}

// ---------------------------------------------------------------------------
// operand prep
// ---------------------------------------------------------------------------
__global__ void split_kernel(const float* __restrict__ in, __nv_bfloat16* __restrict__ hi,
                             __nv_bfloat16* __restrict__ lo, int n) {
    int i = blockIdx.x * 256 + threadIdx.x;
    if (i < n) { __nv_bfloat16 h, l; split2(in[i], h, l); hi[i] = h; lo[i] = l; }
}
__global__ void tsplit_kernel(const float* __restrict__ W, int K, int Nn,
                              __nv_bfloat16* __restrict__ hi, __nv_bfloat16* __restrict__ lo) {
    int i = blockIdx.x * 256 + threadIdx.x;
    if (i < Nn * K) {
        int n = i / K, k = i - n * K;
        __nv_bfloat16 h, l; split2(W[(size_t)k * Nn + n], h, l);
        hi[i] = h; lo[i] = l;
    }
}

// ---------------------------------------------------------------------------
// CSR build
// ---------------------------------------------------------------------------
__global__ void zero2_kernel(int* a, int* b, int n) {
    int i = blockIdx.x * 256 + threadIdx.x;
    if (i < n) { a[i] = 0; b[i] = 0; }
}
__global__ void hist_kernel(const int* __restrict__ dst, int E, int N, int* __restrict__ deg) {
    int e = blockIdx.x * 256 + threadIdx.x;
    if (e < E + N) atomicAdd(&deg[(e < E) ? dst[e] : (e - E)], 1);
}
__global__ void scan_kernel(const int* __restrict__ deg, int* __restrict__ rowptr, int N, int Etot) {
    __shared__ int part[1024];
    int tid = threadIdx.x;
    int chunk = (N + 1023) >> 10;
    int lo = tid * chunk, hi = min(lo + chunk, N);
    int s = 0;
    for (int i = lo; i < hi; i++) s += deg[i];
    part[tid] = s; __syncthreads();
    for (int off = 1; off < 1024; off <<= 1) {
        int v = (tid >= off) ? part[tid - off] : 0;
        __syncthreads(); part[tid] += v; __syncthreads();
    }
    int run = tid ? part[tid - 1] : 0;
    for (int i = lo; i < hi; i++) { rowptr[i] = run; run += deg[i]; }
    if (tid == 0) rowptr[N] = Etot;
}
__global__ void scatter_kernel(const int* __restrict__ src, const int* __restrict__ dst,
                               int E, int N, const int* __restrict__ rowptr,
                               int* __restrict__ cnt, int* __restrict__ csrc) {
    int e = blockIdx.x * 256 + threadIdx.x;
    if (e < E + N) {
        int d, s;
        if (e < E) { d = dst[e]; s = src[e]; } else { d = e - E; s = e - E; }
        csrc[rowptr[d] + atomicAdd(&cnt[d], 1)] = s;
    }
}

// ---------------------------------------------------------------------------
// attention logits (float4)
// ---------------------------------------------------------------------------
template <int H, int C>
__global__ void logits_kernel(const float* __restrict__ hin,
                              const float* __restrict__ a_src, const float* __restrict__ a_dst,
                              float* __restrict__ ss, float* __restrict__ sd) {
    int n = blockIdx.x;
    int warp = threadIdx.x >> 5, lane = threadIdx.x & 31;
    const float* hr = hin + (size_t)n * H * C + warp * C;
    float as_ = 0.f, ad_ = 0.f;
#pragma unroll
    for (int c = lane * 4; c < C; c += 128) {
        float4 v = *reinterpret_cast<const float4*>(hr + c);
        float4 wa = *reinterpret_cast<const float4*>(a_src + warp * C + c);
        float4 wd = *reinterpret_cast<const float4*>(a_dst + warp * C + c);
        as_ += v.x * wa.x + v.y * wa.y + v.z * wa.z + v.w * wa.w;
        ad_ += v.x * wd.x + v.y * wd.y + v.z * wd.z + v.w * wd.w;
    }
#pragma unroll
    for (int o = 16; o; o >>= 1) {
        as_ += __shfl_down_sync(0xFFFFFFFFu, as_, o);
        ad_ += __shfl_down_sync(0xFFFFFFFFu, ad_, o);
    }
    if (lane == 0) { ss[n * H + warp] = as_; sd[n * H + warp] = ad_; }
}

// ---------------------------------------------------------------------------
// attention + ELU, float4 aggregation; fused hi/lo bf16x2 epilogue
// blockDim = H*C/4 (256 for H=4, 64 for H=1)
// ---------------------------------------------------------------------------
__device__ __forceinline__ unsigned fenc(float f) {
    unsigned u = __float_as_uint(f);
    return (u >> 31) ? ~u : (u | 0x80000000u);
}
__device__ __forceinline__ float fdec(unsigned u) {
    return (u >> 31) ? __uint_as_float(u & 0x7FFFFFFFu) : __uint_as_float(~u);
}

template <int H, int C>
__global__ void attn_kernel(const float* __restrict__ hin,
                            const float* __restrict__ s_src, const float* __restrict__ s_dst,
                            const int* __restrict__ rowptr, const int* __restrict__ csrc,
                            float* __restrict__ alpha, const float* __restrict__ bias,
                            float* __restrict__ out,
                            __nv_bfloat16* __restrict__ outhi, __nv_bfloat16* __restrict__ outlo) {
    constexpr int HC = H * C;
    constexpr int BD = HC / 4;
    int n = blockIdx.x, tid = threadIdx.x;
    int base = rowptr[n];
    int deg = rowptr[n + 1] - base;

    __shared__ unsigned smax[H];
    __shared__ float ssum[H], sinv[H];
    if (tid < H) { smax[tid] = 0u; ssum[tid] = 0.f; }
    __syncthreads();

    float sdn[H];
#pragma unroll
    for (int h = 0; h < H; h++) sdn[h] = s_dst[n * H + h];

    int tot = deg * H;
    for (int idx = tid; idx < tot; idx += BD) {
        int j = idx / H, h = idx - (idx / H) * H;
        int s = csrc[base + j];
        float v = s_src[s * H + h] + sdn[h];
        v = v > 0.f ? v : 0.2f * v;
        alpha[(size_t)(base + j) * H + h] = v;
        atomicMax(&smax[h], fenc(v));
    }
    __syncthreads();
    float m[H];
#pragma unroll
    for (int h = 0; h < H; h++) m[h] = fdec(smax[h]);
    for (int idx = tid; idx < tot; idx += BD) {
        int j = idx / H, h = idx - (idx / H) * H;
        size_t p = (size_t)(base + j) * H + h;
        float ex = __expf(alpha[p] - m[h]);
        alpha[p] = ex;
        atomicAdd(&ssum[h], ex);
    }
    __syncthreads();
    if (tid < H) sinv[tid] = 1.f / (ssum[tid] + 1e-16f);
    __syncthreads();

    const int head = (4 * tid) / C;   // constant per thread
    float4 acc = make_float4(0.f, 0.f, 0.f, 0.f);

#pragma unroll 4
    for (int j = 0; j < deg; j++) {
        int s = csrc[base + j];
        float a = alpha[(size_t)(base + j) * H + head];
        float4 hv = *reinterpret_cast<const float4*>(hin + (size_t)s * HC + 4 * tid);
        acc.x = fmaf(hv.x, a, acc.x);
        acc.y = fmaf(hv.y, a, acc.y);
        acc.z = fmaf(hv.z, a, acc.z);
        acc.w = fmaf(hv.w, a, acc.w);
    }

    float inv = sinv[head];
    float4 bv = *reinterpret_cast<const float4*>(bias + 4 * tid);
    float4 v;
    v.x = acc.x * inv + bv.x;
    v.y = acc.y * inv + bv.y;
    v.z = acc.z * inv + bv.z;
    v.w = acc.w * inv + bv.w;
    v.x = v.x > 0.f ? v.x : expm1f(v.x);
    v.y = v.y > 0.f ? v.y : expm1f(v.y);
    v.z = v.z > 0.f ? v.z : expm1f(v.z);
    v.w = v.w > 0.f ? v.w : expm1f(v.w);

    size_t off = (size_t)n * HC + 4 * tid;
    if (out) *reinterpret_cast<float4*>(out + off) = v;
    if (outhi) {
        __nv_bfloat16 h0, l0, h1, l1, h2, l2, h3, l3;
        split2(v.x, h0, l0); split2(v.y, h1, l1);
        split2(v.z, h2, l2); split2(v.w, h3, l3);
        __nv_bfloat162* ph = reinterpret_cast<__nv_bfloat162*>(outhi + off);
        __nv_bfloat162* pl = reinterpret_cast<__nv_bfloat162*>(outlo + off);
        ph[0] = __nv_bfloat162(h0, h1); ph[1] = __nv_bfloat162(h2, h3);
        pl[0] = __nv_bfloat162(l0, l1); pl[1] = __nv_bfloat162(l2, l3);
    }
}

// ---------------------------------------------------------------------------
// mean pool + influence head
// ---------------------------------------------------------------------------
__global__ void zerof_kernel(float* a, int n) {
    int i = blockIdx.x * 256 + threadIdx.x;
    if (i < n) a[i] = 0.f;
}
__global__ void mean_kernel(const float* __restrict__ h, float* __restrict__ gf, int N) {
    int c = threadIdx.x;
    int rows = (N + gridDim.x - 1) / gridDim.x;
    int r0 = blockIdx.x * rows, r1 = min(r0 + rows, N);
    float s = 0.f;
    for (int r = r0; r < r1; r++) s += h[(size_t)r * 256 + c];
    atomicAdd(&gf[c], s / (float)N);
}
__global__ void infl_kernel(const float* __restrict__ t, const float* __restrict__ Wp2,
                            const float* __restrict__ bp2, float* __restrict__ infl, int N) {
    int g = blockIdx.x * blockDim.x + threadIdx.x;
    int n = g >> 5, lane = g & 31;
    if (n >= N) return;
    float4 tv = reinterpret_cast<const float4*>(t + (size_t)n * 128)[lane];
    float4 wv = reinterpret_cast<const float4*>(Wp2)[lane];
    float s = tv.x * wv.x + tv.y * wv.y + tv.z * wv.z + tv.w * wv.w;
#pragma unroll
    for (int o = 16; o; o >>= 1) s += __shfl_down_sync(0xFFFFFFFFu, s, o);
    if (lane == 0) infl[n] = 1.f / (1.f + __expf(-(s + bp2[0])));
}

// ---------------------------------------------------------------------------
extern "C" void kernel_launch(void* const* d_in, const int* in_sizes, int n_in,
                              void* d_out, int out_size) {
    const float* x      = (const float*)d_in[0];
    const int*   ei     = (const int*)d_in[1];
    const float* W1     = (const float*)d_in[2];
    const float* a_src1 = (const float*)d_in[3];
    const float* a_dst1 = (const float*)d_in[4];
    const float* b1     = (const float*)d_in[5];
    const float* W2     = (const float*)d_in[6];
    const float* a_src2 = (const float*)d_in[7];
    const float* a_dst2 = (const float*)d_in[8];
    const float* b2     = (const float*)d_in[9];
    const float* Wp1    = (const float*)d_in[10];
    const float* bp1    = (const float*)d_in[11];
    const float* Wp2    = (const float*)d_in[12];
    const float* bp2    = (const float*)d_in[13];

    int N = in_sizes[0] / 384;
    int E = in_sizes[1] / 2;
    int Etot = E + N;

    float *h1, *h2, *t, *alpha, *ss, *sd;
    __nv_bfloat16 *xh, *xl, *h1ph, *h1pl, *hh, *hl, *w1h, *w1l, *w2h, *w2l, *wph, *wpl;
    int *deg, *cnt, *rowptr, *csrc;
    cudaGetSymbolAddress((void**)&h1, g_h1);
    cudaGetSymbolAddress((void**)&h2, g_h2);
    cudaGetSymbolAddress((void**)&t, g_t);
    cudaGetSymbolAddress((void**)&alpha, g_alpha);
    cudaGetSymbolAddress((void**)&ss, g_ss);
    cudaGetSymbolAddress((void**)&sd, g_sd);
    cudaGetSymbolAddress((void**)&xh, g_xh);
    cudaGetSymbolAddress((void**)&xl, g_xl);
    cudaGetSymbolAddress((void**)&h1ph, g_h1ph);
    cudaGetSymbolAddress((void**)&h1pl, g_h1pl);
    cudaGetSymbolAddress((void**)&hh, g_hh);
    cudaGetSymbolAddress((void**)&hl, g_hl);
    cudaGetSymbolAddress((void**)&w1h, g_w1h);
    cudaGetSymbolAddress((void**)&w1l, g_w1l);
    cudaGetSymbolAddress((void**)&w2h, g_w2h);
    cudaGetSymbolAddress((void**)&w2l, g_w2l);
    cudaGetSymbolAddress((void**)&wph, g_wph);
    cudaGetSymbolAddress((void**)&wpl, g_wpl);
    cudaGetSymbolAddress((void**)&deg, g_deg);
    cudaGetSymbolAddress((void**)&cnt, g_cnt);
    cudaGetSymbolAddress((void**)&rowptr, g_rowptr);
    cudaGetSymbolAddress((void**)&csrc, g_csrc);

    float* out_h  = (float*)d_out;
    float* out_gf = out_h + (size_t)N * 256;
    float* out_in = out_gf + 256;

    cudaFuncSetAttribute(hmma_gemm_kernel, cudaFuncAttributeMaxDynamicSharedMemorySize, 3 * 40960);

    int eb = (Etot + 255) / 256;
    int nb = (N + 255) / 256;
    int mtiles = (N + 127) / 128;

    // operand prep
    split_kernel<<<(N * 384 + 255) / 256, 256>>>(x, xh, xl, N * 384);
    tsplit_kernel<<<(1024 * 384 + 255) / 256, 256>>>(W1, 384, 1024, w1h, w1l);
    tsplit_kernel<<<(256 * 1024 + 255) / 256, 256>>>(W2, 1024, 256, w2h, w2l);
    tsplit_kernel<<<(128 * 256 + 255) / 256, 256>>>(Wp1, 256, 128, wph, wpl);

    // CSR build
    zero2_kernel<<<nb, 256>>>(deg, cnt, N);
    hist_kernel<<<eb, 256>>>(ei + E, E, N, deg);
    scan_kernel<<<1, 1024>>>(deg, rowptr, N, Etot);
    scatter_kernel<<<eb, 256>>>(ei, ei + E, E, N, rowptr, cnt, csrc);

    // Layer 1: h1 = x @ W1  [N,1024], K=384
    {
        dim3 g(1024 / 128, mtiles);
        hmma_gemm_kernel<<<g, 256, 3 * 40960>>>(xh, xl, w1h, w1l, h1, N, 1024, 384, nullptr, 0);
    }
    logits_kernel<4, 256><<<N, 128>>>(h1, a_src1, a_dst1, ss, sd);
    attn_kernel<4, 256><<<N, 256>>>(h1, ss, sd, rowptr, csrc, alpha, b1, nullptr, h1ph, h1pl);

    // Layer 2: h2 = h1p @ W2  [N,256], K=1024
    {
        dim3 g(256 / 128, mtiles);
        hmma_gemm_kernel<<<g, 256, 3 * 40960>>>(h1ph, h1pl, w2h, w2l, h2, N, 256, 1024, nullptr, 0);
    }
    logits_kernel<1, 256><<<N, 32>>>(h2, a_src2, a_dst2, ss, sd);
    attn_kernel<1, 256><<<N, 64>>>(h2, ss, sd, rowptr, csrc, alpha, b2, out_h, hh, hl);

    // pooling
    zerof_kernel<<<1, 256>>>(out_gf, 256);
    mean_kernel<<<128, 256>>>(out_h, out_gf, N);

    // influence MLP: t = relu(h @ Wp1 + bp1)  [N,128], K=256
    {
        dim3 g(128 / 128, mtiles);
        hmma_gemm_kernel<<<g, 256, 3 * 40960>>>(hh, hl, wph, wpl, t, N, 128, 256, bp1, 1);
    }
    infl_kernel<<<(N * 32 + 255) / 256, 256>>>(t, Wp2, bp2, out_in, N);
}